// round 10
// baseline (speedup 1.0000x reference)
#include <cuda_runtime.h>
#include <cuda_bf16.h>
#include <cstdint>
#include <cstddef>

#define T_STEPS 512
#define B_SZ    256
#define NO_SZ   128

// ---------------------------------------------------------------------------
// Static scratch.
//   g_G    [tile][b][r]   fp32 preacts (gsum folds slow C streams in place)
//   g_Hep  [tile][b][k]   fp32 hidden epochs (finalH output only)
//   g_HpH/L[tile][b][k]   bf16 hi/lo hidden epochs (GEMM B operands)
//   g_R    [tile][b][o]   prefix-summed output projections
//   g_C    [ctile][b][r]  off-diagonal recurrent projections
//   g_W*H/L, g_XH/L       pre-packed bf16 hi/lo fragment words
// ---------------------------------------------------------------------------
__device__ float g_G  [1020u * 64  * 256];
__device__ float g_Hep[1020u * 64  * 256];
__device__ float g_R  [1020u * 128 * 256];
__device__ float g_C  [988u  * 64  * 256];

__device__ __align__(16) uint32_t g_WhH[512 * 256], g_WhL[512 * 256];
__device__ __align__(16) uint32_t g_WiH[512 * 64],  g_WiL[512 * 64];
__device__ __align__(16) uint32_t g_WoH[128 * 256], g_WoL[128 * 256];
__device__ __align__(16) uint32_t g_XH[512u * 256 * 64], g_XL[512u * 256 * 64];
__device__ __align__(16) uint16_t g_HpH[1020u * 256 * 64], g_HpL[1020u * 256 * 64];

__device__ __constant__ int c_S[8] = {0, 0, 256, 512, 704, 832, 912, 960};

__device__ __forceinline__ int hb(int j) { return 1024 - (1024 >> j); }

__device__ __forceinline__ float ftanh(float x) {
    float t = __expf(2.0f * x);
    return 1.0f - __fdividef(2.0f, t + 1.0f);
}

__device__ __forceinline__ void mma_bf16(float* d, const uint32_t* a, const uint32_t* b)
{
    asm volatile(
        "mma.sync.aligned.m16n8k16.row.col.f32.bf16.bf16.f32 "
        "{%0,%1,%2,%3},{%4,%5,%6,%7},{%8,%9},{%0,%1,%2,%3};\n"
        : "+f"(d[0]), "+f"(d[1]), "+f"(d[2]), "+f"(d[3])
        : "r"(a[0]), "r"(a[1]), "r"(a[2]), "r"(a[3]), "r"(b[0]), "r"(b[1]));
}

__device__ __forceinline__ uint32_t pack2(float x0, float x1, bool lo)
{
    __nv_bfloat16 h0 = __float2bfloat16(x0);
    __nv_bfloat16 h1 = __float2bfloat16(x1);
    if (lo) {
        h0 = __float2bfloat16(x0 - __bfloat162float(h0));
        h1 = __float2bfloat16(x1 - __bfloat162float(h1));
    }
    __nv_bfloat162 p = __halves2bfloat162(h0, h1);
    return *reinterpret_cast<uint32_t*>(&p);
}

// Shared layout (uint32 words), total 9216 words = 36864 B:
//   AH [64][36] @0   AL [64][36] @2304   BH [64][36] @4608   BL [64][36] @6912
//   S  (float [64][68]) overlays BH/BL region
#define AH_OFF 0
#define AL_OFF 2304
#define BH_OFF 4608
#define BL_OFF 6912

// ---- float staging (g0_hi only) -------------------------------------------
__device__ __forceinline__ void stage_AB(uint32_t* su,
                                         const float* __restrict__ Ag, int lda, int koff,
                                         const float* __restrict__ Bg, int ldb,
                                         int tid)
{
    for (int idx = tid; idx < 64 * 32; idx += 256) {
        int r = idx >> 5, p = idx & 31;
        float x0 = Ag[(size_t)r * lda + koff + 2 * p];
        float x1 = Ag[(size_t)r * lda + koff + 2 * p + 1];
        su[AH_OFF + r * 36 + p] = pack2(x0, x1, false);
        su[AL_OFF + r * 36 + p] = pack2(x0, x1, true);
    }
    for (int idx = tid; idx < 64 * 16; idx += 256) {
        int c = idx >> 4, q = idx & 15;
        float4 v = *(const float4*)&Bg[(size_t)c * ldb + koff + 4 * q];
        su[BH_OFF + c * 36 + 2 * q]     = pack2(v.x, v.y, false);
        su[BL_OFF + c * 36 + 2 * q]     = pack2(v.x, v.y, true);
        su[BH_OFF + c * 36 + 2 * q + 1] = pack2(v.z, v.w, false);
        su[BL_OFF + c * 36 + 2 * q + 1] = pack2(v.z, v.w, true);
    }
}

// ---- packed staging (pure uint4 copies, no conversions) --------------------
__device__ __forceinline__ void stage_packed(uint32_t* su,
    const uint32_t* __restrict__ AHp, const uint32_t* __restrict__ ALp, int ldaw, int kwA,
    const uint32_t* __restrict__ BHp, const uint32_t* __restrict__ BLp, int ldbw, int kwB,
    int tid)
{
    for (int idx = tid; idx < 512; idx += 256) {
        int r = idx >> 3, p4 = (idx & 7) * 4;
        *(uint4*)&su[AH_OFF + r * 36 + p4] = *(const uint4*)&AHp[(size_t)r * ldaw + kwA + p4];
        *(uint4*)&su[AL_OFF + r * 36 + p4] = *(const uint4*)&ALp[(size_t)r * ldaw + kwA + p4];
    }
    for (int idx = tid; idx < 512; idx += 256) {
        int c = idx >> 3, p4 = (idx & 7) * 4;
        *(uint4*)&su[BH_OFF + c * 36 + p4] = *(const uint4*)&BHp[(size_t)c * ldbw + kwB + p4];
        *(uint4*)&su[BL_OFF + c * 36 + p4] = *(const uint4*)&BLp[(size_t)c * ldbw + kwB + p4];
    }
}

// 64x64 tile MMA: warp w -> rows (w&3)*16.., cols (w>>2)*32..; acc[4][4]
__device__ __forceinline__ void mma_block(const uint32_t* su, int warp, int lane,
                                          float (&acc)[4][4])
{
    const int mrow = (warp & 3) * 16;
    const int nb   = (warp >> 2) * 32;
    const int gr   = lane >> 2, tg = lane & 3;
#pragma unroll
    for (int c = 0; c < 4; c++) {
        const int pb = c * 8;
        uint32_t ah[4], al[4];
        ah[0] = su[AH_OFF + (mrow + gr)     * 36 + pb + tg];
        ah[1] = su[AH_OFF + (mrow + gr + 8) * 36 + pb + tg];
        ah[2] = su[AH_OFF + (mrow + gr)     * 36 + pb + 4 + tg];
        ah[3] = su[AH_OFF + (mrow + gr + 8) * 36 + pb + 4 + tg];
        al[0] = su[AL_OFF + (mrow + gr)     * 36 + pb + tg];
        al[1] = su[AL_OFF + (mrow + gr + 8) * 36 + pb + tg];
        al[2] = su[AL_OFF + (mrow + gr)     * 36 + pb + 4 + tg];
        al[3] = su[AL_OFF + (mrow + gr + 8) * 36 + pb + 4 + tg];
#pragma unroll
        for (int nt = 0; nt < 4; nt++) {
            const int colb = nb + nt * 8 + gr;
            uint32_t bh[2], bl[2];
            bh[0] = su[BH_OFF + colb * 36 + pb + tg];
            bh[1] = su[BH_OFF + colb * 36 + pb + 4 + tg];
            bl[0] = su[BL_OFF + colb * 36 + pb + tg];
            bl[1] = su[BL_OFF + colb * 36 + pb + 4 + tg];
            mma_bf16(acc[nt], ah, bh);
            mma_bf16(acc[nt], ah, bl);
            mma_bf16(acc[nt], al, bh);
        }
    }
}

// acc -> S[col][row] transpose staging (S overlays B smem region)
__device__ __forceinline__ void acc_to_S(float* Sf, int warp, int lane, float (&acc)[4][4])
{
    const int mrow = (warp & 3) * 16;
    const int nb   = (warp >> 2) * 32;
    const int gr   = lane >> 2, tg = lane & 3;
#pragma unroll
    for (int nt = 0; nt < 4; nt++) {
        const int c0 = nb + nt * 8 + 2 * tg;
        Sf[(size_t)c0       * 68 + mrow + gr]     = acc[nt][0];
        Sf[(size_t)(c0 + 1) * 68 + mrow + gr]     = acc[nt][1];
        Sf[(size_t)c0       * 68 + mrow + gr + 8] = acc[nt][2];
        Sf[(size_t)(c0 + 1) * 68 + mrow + gr + 8] = acc[nt][3];
    }
}

// ---------------------------------------------------------------------------
// packW: Wh/Wi/Wo -> bf16 hi/lo fragment words.  grid 768 x 256.
// ---------------------------------------------------------------------------
__global__ void __launch_bounds__(256) packW_kernel(const float* __restrict__ Wh,
                                                    const float* __restrict__ Wi,
                                                    const float* __restrict__ Wo)
{
    int idx = blockIdx.x * 256 + threadIdx.x;
    if (idx < 131072) {                       // Wh: 512 rows x 256 words
        int row = idx >> 8, p = idx & 255;
        float x0 = Wh[(size_t)row * 513 + 2 * p];
        float x1 = Wh[(size_t)row * 513 + 2 * p + 1];
        g_WhH[idx] = pack2(x0, x1, false);
        g_WhL[idx] = pack2(x0, x1, true);
    } else if (idx < 163840) {                // Wi: 512 rows x 64 words
        int k = idx - 131072;
        int row = k >> 6, p = k & 63;
        float x0 = Wi[(size_t)row * 129 + 2 * p];
        float x1 = Wi[(size_t)row * 129 + 2 * p + 1];
        g_WiH[k] = pack2(x0, x1, false);
        g_WiL[k] = pack2(x0, x1, true);
    } else if (idx < 196608) {                // Wo: 128 rows x 256 words
        int k = idx - 163840;
        int row = k >> 8, p = k & 255;
        float x0 = Wo[(size_t)row * 513 + 2 * p];
        float x1 = Wo[(size_t)row * 513 + 2 * p + 1];
        g_WoH[k] = pack2(x0, x1, false);
        g_WoL[k] = pack2(x0, x1, true);
    }
}

// ---------------------------------------------------------------------------
// packX: X -> bf16 hi/lo words [row = t*256+b][64 words].  grid 8192 x 256.
// ---------------------------------------------------------------------------
__global__ void __launch_bounds__(256) packX_kernel(const float* __restrict__ X)
{
    size_t w4 = ((size_t)blockIdx.x * 256 + threadIdx.x) * 4;  // 4 words/thread
    size_t row = w4 >> 6;
    int p = (int)(w4 & 63);
    const float* xr = X + row * 128 + 2 * p;
    float4 a = *(const float4*)xr;
    float4 b = *(const float4*)(xr + 4);
    uint4 h, l;
    h.x = pack2(a.x, a.y, false); l.x = pack2(a.x, a.y, true);
    h.y = pack2(a.z, a.w, false); l.y = pack2(a.z, a.w, true);
    h.z = pack2(b.x, b.y, false); l.z = pack2(b.x, b.y, true);
    h.w = pack2(b.z, b.w, false); l.w = pack2(b.z, b.w, true);
    *(uint4*)&g_XH[w4] = h;
    *(uint4*)&g_XL[w4] = l;
}

// ---------------------------------------------------------------------------
// Shared epilogue: write fp32 tile (b-major, r contiguous)
// ---------------------------------------------------------------------------
__device__ __forceinline__ void store_tile64(float* __restrict__ out, const float* Sf, int tid)
{
    for (int i = tid; i < 64 * 16; i += 256) {
        int col = i >> 4, rq = i & 15;
        *(float4*)&out[(size_t)col * 64 + rq * 4] = *(float4*)&Sf[(size_t)col * 68 + rq * 4];
    }
}

// ---------------------------------------------------------------------------
// g0f: float-staged input projection (hi tiles, on-path start).
// ---------------------------------------------------------------------------
__global__ void __launch_bounds__(256) g0f_kernel(const float* __restrict__ X,
                                                  const float* __restrict__ Wi,
                                                  const float* __restrict__ Wh,
                                                  int idx0)
{
    __shared__ __align__(16) uint32_t su[9216];
    float* Sf = (float*)(su + BH_OFF);

    const int idx = idx0 + blockIdx.x;
    const int v   = 1024 - idx;
    const int c   = __clz(v - 1) - 22;
    const int m   = idx - (1024 - (1024 >> c));
    const int t   = m << c;
    const int b0  = blockIdx.y * 64;
    const int tid = threadIdx.x;
    const int warp = tid >> 5, lane = tid & 31;

    float acc[4][4];
#pragma unroll
    for (int q = 0; q < 4; q++)
#pragma unroll
        for (int u = 0; u < 4; u++) acc[q][u] = 0.f;

    for (int kh = 0; kh < 2; kh++) {
        stage_AB(su, Wi + (size_t)(c * 64) * 129, 129, kh * 64,
                 X + ((size_t)t * 256 + b0) * 128, 128, tid);
        __syncthreads();
        mma_block(su, warp, lane, acc);
        __syncthreads();
    }

    {
        const int mrow = (warp & 3) * 16, gr = lane >> 2;
        int r0 = c * 64 + mrow + gr, r1 = r0 + 8;
        float ba = Wi[(size_t)r0 * 129 + 128] + Wh[(size_t)r0 * 513 + 512];
        float bb = Wi[(size_t)r1 * 129 + 128] + Wh[(size_t)r1 * 513 + 512];
#pragma unroll
        for (int nt = 0; nt < 4; nt++) {
            acc[nt][0] += ba; acc[nt][1] += ba;
            acc[nt][2] += bb; acc[nt][3] += bb;
        }
    }

    acc_to_S(Sf, warp, lane, acc);
    __syncthreads();
    store_tile64(g_G + (size_t)idx * 16384 + (size_t)b0 * 64, Sf, tid);
}

// ---------------------------------------------------------------------------
// g0p: packed-staged input projection (bulk, off-path after packW/packX).
// ---------------------------------------------------------------------------
__global__ void __launch_bounds__(256) g0p_kernel(const float* __restrict__ Wi,
                                                  const float* __restrict__ Wh,
                                                  int idx0)
{
    __shared__ __align__(16) uint32_t su[9216];
    float* Sf = (float*)(su + BH_OFF);

    const int idx = idx0 + blockIdx.x;
    const int v   = 1024 - idx;
    const int c   = __clz(v - 1) - 22;
    const int m   = idx - (1024 - (1024 >> c));
    const int t   = m << c;
    const int b0  = blockIdx.y * 64;
    const int tid = threadIdx.x;
    const int warp = tid >> 5, lane = tid & 31;

    float acc[4][4];
#pragma unroll
    for (int q = 0; q < 4; q++)
#pragma unroll
        for (int u = 0; u < 4; u++) acc[q][u] = 0.f;

    for (int kh = 0; kh < 2; kh++) {
        stage_packed(su, g_WiH + (size_t)(c * 64) * 64, g_WiL + (size_t)(c * 64) * 64, 64, kh * 32,
                     g_XH + ((size_t)t * 256 + b0) * 64, g_XL + ((size_t)t * 256 + b0) * 64, 64, kh * 32,
                     tid);
        __syncthreads();
        mma_block(su, warp, lane, acc);
        __syncthreads();
    }

    {
        const int mrow = (warp & 3) * 16, gr = lane >> 2;
        int r0 = c * 64 + mrow + gr, r1 = r0 + 8;
        float ba = Wi[(size_t)r0 * 129 + 128] + Wh[(size_t)r0 * 513 + 512];
        float bb = Wi[(size_t)r1 * 129 + 128] + Wh[(size_t)r1 * 513 + 512];
#pragma unroll
        for (int nt = 0; nt < 4; nt++) {
            acc[nt][0] += ba; acc[nt][1] += ba;
            acc[nt][2] += bb; acc[nt][3] += bb;
        }
    }

    acc_to_S(Sf, warp, lane, acc);
    __syncthreads();
    store_tile64(g_G + (size_t)idx * 16384 + (size_t)b0 * 64, Sf, tid);
}

// ---------------------------------------------------------------------------
// projC: C[z][j][e] = Wh[z-rows, j-cols] @ H_j[e],  z = zbase + blockIdx.z.
// ---------------------------------------------------------------------------
__global__ void __launch_bounds__(256) projC_kernel(int j, int zbase)
{
    __shared__ __align__(16) uint32_t su[9216];
    float* Sf = (float*)(su + BH_OFF);

    const int e   = blockIdx.x;
    const int U   = gridDim.x;
    const int b0  = blockIdx.y * 64;
    const int z   = zbase + blockIdx.z;
    const int tid = threadIdx.x;
    const int warp = tid >> 5, lane = tid & 31;

    const size_t hrow = ((size_t)(hb(j) + e) * 256 + b0) * 32;

    float acc[4][4];
#pragma unroll
    for (int q = 0; q < 4; q++)
#pragma unroll
        for (int u = 0; u < 4; u++) acc[q][u] = 0.f;

    stage_packed(su, g_WhH + (size_t)(z * 64) * 256, g_WhL + (size_t)(z * 64) * 256, 256, j * 32,
                 (const uint32_t*)g_HpH + hrow, (const uint32_t*)g_HpL + hrow, 32, 0, tid);
    __syncthreads();
    mma_block(su, warp, lane, acc);
    __syncthreads();
    acc_to_S(Sf, warp, lane, acc);
    __syncthreads();

    store_tile64(g_C + (size_t)(c_S[j] + z * U + e) * 16384 + (size_t)b0 * 64, Sf, tid);
}

// ---------------------------------------------------------------------------
// gsum: G'[m] = G[m] + sum_{j >= C+2} C[C][j][(m-1)>>(j-C)]   (m >= 1)
// ---------------------------------------------------------------------------
__global__ void __launch_bounds__(256) gsum_kernel(int C)
{
    const int m   = blockIdx.x + 1;
    const int b0  = blockIdx.y * 64;
    const int tid = threadIdx.x;
    const int HB  = 1024 - (1024 >> C);

    float* Gt = g_G + (size_t)(HB + m) * 16384 + (size_t)b0 * 64;

    const float* Ct[6];
    int ns = 0;
    for (int j = C + 2; j < 8; j++) {
        int e = (m - 1) >> (j - C);
        Ct[ns++] = g_C + (size_t)(c_S[j] + C * (512 >> j) + e) * 16384 + (size_t)b0 * 64;
    }

    for (int i = tid; i < 1024; i += 256) {
        float4 a = *(float4*)&Gt[i * 4];
        for (int s = 0; s < ns; s++) {
            float4 v = *(const float4*)&Ct[s][i * 4];
            a.x += v.x; a.y += v.y; a.z += v.z; a.w += v.w;
        }
        *(float4*)&Gt[i * 4] = a;
    }
}

// ---------------------------------------------------------------------------
// projR: R_j[e] rows z*64.. = Wo[rows, j-cols] @ H_j[e] + R_{j+1}[e>>1]
//        (+Wo bias at j=7; tanh->Y at j=0).
// ---------------------------------------------------------------------------
__global__ void __launch_bounds__(256) projR_kernel(const float* __restrict__ Wo,
                                                    float* __restrict__ Y, int j)
{
    __shared__ __align__(16) uint32_t su[9216];
    float* Sf = (float*)(su + BH_OFF);

    const int e   = blockIdx.x;
    const int b0  = blockIdx.y * 64;
    const int z   = blockIdx.z;
    const int tid = threadIdx.x;
    const int warp = tid >> 5, lane = tid & 31;

    const size_t hrow = ((size_t)(hb(j) + e) * 256 + b0) * 32;

    float acc[4][4];
#pragma unroll
    for (int q = 0; q < 4; q++)
#pragma unroll
        for (int u = 0; u < 4; u++) acc[q][u] = 0.f;

    stage_packed(su, g_WoH + (size_t)(z * 64) * 256, g_WoL + (size_t)(z * 64) * 256, 256, j * 32,
                 (const uint32_t*)g_HpH + hrow, (const uint32_t*)g_HpL + hrow, 32, 0, tid);
    __syncthreads();
    mma_block(su, warp, lane, acc);
    __syncthreads();
    acc_to_S(Sf, warp, lane, acc);
    __syncthreads();

    const int o0 = z * 64;
    const float* Rpar = (j < 7)
        ? g_R + (size_t)(hb(j + 1) + (e >> 1)) * 32768
        : nullptr;
    for (int i = tid; i < 64 * 16; i += 256) {
        int col = i >> 4, rq = i & 15;
        float4 s = *(float4*)&Sf[(size_t)col * 68 + rq * 4];
        if (j < 7) {
            float4 p = *(const float4*)&Rpar[(size_t)(b0 + col) * 128 + o0 + rq * 4];
            s.x += p.x; s.y += p.y; s.z += p.z; s.w += p.w;
        } else {
            s.x += Wo[(size_t)(o0 + rq * 4 + 0) * 513 + 512];
            s.y += Wo[(size_t)(o0 + rq * 4 + 1) * 513 + 512];
            s.z += Wo[(size_t)(o0 + rq * 4 + 2) * 513 + 512];
            s.w += Wo[(size_t)(o0 + rq * 4 + 3) * 513 + 512];
        }
        if (j == 0) {
            float4 y = make_float4(ftanh(s.x), ftanh(s.y), ftanh(s.z), ftanh(s.w));
            *(float4*)&Y[((size_t)e * 256 + b0 + col) * 128 + o0 + rq * 4] = y;
        } else {
            *(float4*)&g_R[(size_t)(hb(j) + e) * 32768 +
                           (size_t)(b0 + col) * 128 + o0 + rq * 4] = s;
        }
    }
}

// ---------------------------------------------------------------------------
// seq<C>: H[m] = tanh(G'[m] + C1[(m-1)>>1] + W_CC @ H[m-1]); emits fp32 +
// packed bf16 hi/lo H.  grid 128 x 2 batch cols, 128 threads, prefetch 8.
// ---------------------------------------------------------------------------
template <int C>
__global__ void __launch_bounds__(128) seq_kernel(const float* __restrict__ Wh)
{
    constexpr int  U    = 512 >> C;
    constexpr bool HASC = (C < 7);
    constexpr int  HB   = 1024 - (1024 >> C);
    constexpr int  csl[8] = {0, 0, 256, 512, 704, 832, 912, 960};
    constexpr int  C1B  = HASC ? (csl[C + 1] + C * (512 >> (C + 1))) : 0;
    constexpr int  D    = (U < 8) ? U : 8;

    const int tid = threadIdx.x;
    const int lb  = tid >> 6;
    const int r   = tid & 63;
    const int b   = blockIdx.x * 2 + lb;
    const int off = b * 64 + r;

    __shared__ float Ws[64][65];
    __shared__ float Hs[2][2][64];

    for (int i = tid; i < 4096; i += 128)
        Ws[i >> 6][i & 63] = Wh[(size_t)(C * 64 + (i >> 6)) * 513 + C * 64 + (i & 63)];
    __syncthreads();

    float w[64];
#pragma unroll
    for (int q = 0; q < 64; q++) w[q] = Ws[r][q];

    const float* Gb  = g_G + (size_t)HB * 16384;
    const float* Cb  = g_C + (size_t)C1B * 16384;
    float*       Hbp = g_Hep + (size_t)HB * 16384;
    uint16_t*    HpH = g_HpH + (size_t)HB * 16384;
    uint16_t*    HpL = g_HpL + (size_t)HB * 16384;

    float gv[D], cv[D];
#pragma unroll
    for (int i = 0; i < D; i++) {
        gv[i] = Gb[(size_t)i * 16384 + off];
        cv[i] = 0.f;
        if (HASC && i >= 1) cv[i] = Cb[(size_t)((i - 1) >> 1) * 16384 + off];
    }

    for (int m0 = 0; m0 < U; m0 += D) {
#pragma unroll
        for (int i = 0; i < D; i++) {
            const int m  = m0 + i;
            const int rb = m & 1;
            float a = gv[i];
            if (m > 0) {
                float a0 = 0.f, a1 = 0.f, a2 = 0.f, a3 = 0.f;
#pragma unroll
                for (int q = 0; q < 64; q += 4) {
                    float4 hv = *(const float4*)&Hs[rb][lb][q];
                    a0 += w[q + 0] * hv.x;
                    a1 += w[q + 1] * hv.y;
                    a2 += w[q + 2] * hv.z;
                    a3 += w[q + 3] * hv.w;
                }
                a += (a0 + a1) + (a2 + a3);
                if (HASC) a += cv[i];
            }
            float h = ftanh(a);
            Hbp[(size_t)m * 16384 + off] = h;
            __nv_bfloat16 hh = __float2bfloat16(h);
            __nv_bfloat16 hl = __float2bfloat16(h - __bfloat162float(hh));
            HpH[(size_t)m * 16384 + off] = *reinterpret_cast<uint16_t*>(&hh);
            HpL[(size_t)m * 16384 + off] = *reinterpret_cast<uint16_t*>(&hl);
            Hs[rb ^ 1][lb][r] = h;
            const int mf = m + D;
            if (mf < U) {
                gv[i] = Gb[(size_t)mf * 16384 + off];
                if (HASC) cv[i] = Cb[(size_t)((mf - 1) >> 1) * 16384 + off];
            }
            __syncthreads();
        }
    }
}

// ---------------------------------------------------------------------------
// final H: out[T*B*NO + (j*64+r)*256 + b] = H_j[last epoch][b][r] (transpose)
// ---------------------------------------------------------------------------
__global__ void __launch_bounds__(256) finalH_kernel(float* __restrict__ out)
{
    __shared__ float S[64][65];
    const int j   = blockIdx.x;
    const int b0  = blockIdx.y * 64;
    const int tid = threadIdx.x;
    const int e   = (512 >> j) - 1;
    const float* Hj = g_Hep + (size_t)(hb(j) + e) * 16384;

    for (int i = tid; i < 4096; i += 256) {
        int rr = i & 63, bb = i >> 6;
        S[bb][rr] = Hj[(size_t)(b0 + bb) * 64 + rr];
    }
    __syncthreads();
    for (int i = tid; i < 4096; i += 256) {
        int bb = i & 63, rr = i >> 6;
        out[(size_t)T_STEPS * B_SZ * NO_SZ + (size_t)(j * 64 + rr) * 256 + b0 + bb] =
            S[bb][rr];
    }
}

// ---------------------------------------------------------------------------
// Launch.
//   main: g0f_hi -> seq<j> -> projC(urgent z=j-1) -> ...
//   s1  : packW -> [evPk] -> packX -> g0p (levels 3..0) -> [evG0]
//   s2  : projR chain (R_7..R_0 -> Y), gated evPk + evH[j], join at end
//   s3  : projC deferred + gsum<C>; gated evPk + evH[j]; seq<C> gates evGS[C]
// ---------------------------------------------------------------------------
static cudaStream_t s_s1 = nullptr, s_s2 = nullptr, s_s3 = nullptr;
static cudaEvent_t  s_ev0, s_evPk, s_evG0, s_evH[8], s_evR0, s_evGS[6];
static int s_state = 0;

static bool ensure_streams()
{
    if (s_state) return s_state > 0;
    bool ok = true;
    ok &= cudaStreamCreateWithFlags(&s_s1, cudaStreamNonBlocking) == cudaSuccess;
    ok &= cudaStreamCreateWithFlags(&s_s2, cudaStreamNonBlocking) == cudaSuccess;
    ok &= cudaStreamCreateWithFlags(&s_s3, cudaStreamNonBlocking) == cudaSuccess;
    ok &= cudaEventCreateWithFlags(&s_ev0,  cudaEventDisableTiming) == cudaSuccess;
    ok &= cudaEventCreateWithFlags(&s_evPk, cudaEventDisableTiming) == cudaSuccess;
    ok &= cudaEventCreateWithFlags(&s_evG0, cudaEventDisableTiming) == cudaSuccess;
    ok &= cudaEventCreateWithFlags(&s_evR0, cudaEventDisableTiming) == cudaSuccess;
    for (int i = 0; i < 8; i++)
        ok &= cudaEventCreateWithFlags(&s_evH[i], cudaEventDisableTiming) == cudaSuccess;
    for (int i = 0; i < 6; i++)
        ok &= cudaEventCreateWithFlags(&s_evGS[i], cudaEventDisableTiming) == cudaSuccess;
    s_state = ok ? 1 : -1;
    return ok;
}

extern "C" void kernel_launch(void* const* d_in, const int* in_sizes, int n_in,
                              void* d_out, int out_size)
{
    const float* X  = nullptr;
    const float* Wi = nullptr;
    const float* Wh = nullptr;
    const float* Wo = nullptr;
    for (int i = 0; i < n_in; i++) {
        switch (in_sizes[i]) {
            case 512 * 256 * 128: X  = (const float*)d_in[i]; break;
            case 512 * 129:       Wi = (const float*)d_in[i]; break;
            case 512 * 513:       Wh = (const float*)d_in[i]; break;
            case 128 * 513:       Wo = (const float*)d_in[i]; break;
            default: break;
        }
    }
    float* out = (float*)d_out;

    if (!ensure_streams()) {
        // -------- Fallback: single-stream chain ----------------------------
        packW_kernel<<<768, 256>>>(Wh, Wi, Wo);
        packX_kernel<<<8192, 256>>>(X);
        g0p_kernel<<<dim3(1020, 4), 256>>>(Wi, Wh, 0);
        seq_kernel<7><<<128, 128>>>(Wh);
        projR_kernel<<<dim3(4, 4, 2), 256>>>(Wo, out, 7);
        projC_kernel<<<dim3(4, 4, 7), 256>>>(7, 0);
        seq_kernel<6><<<128, 128>>>(Wh);
        projR_kernel<<<dim3(8, 4, 2), 256>>>(Wo, out, 6);
        projC_kernel<<<dim3(8, 4, 6), 256>>>(6, 0);
        gsum_kernel<<<dim3(15, 4), 256>>>(5);
        seq_kernel<5><<<128, 128>>>(Wh);
        projR_kernel<<<dim3(16, 4, 2), 256>>>(Wo, out, 5);
        projC_kernel<<<dim3(16, 4, 5), 256>>>(5, 0);
        gsum_kernel<<<dim3(31, 4), 256>>>(4);
        seq_kernel<4><<<128, 128>>>(Wh);
        projR_kernel<<<dim3(32, 4, 2), 256>>>(Wo, out, 4);
        projC_kernel<<<dim3(32, 4, 4), 256>>>(4, 0);
        gsum_kernel<<<dim3(63, 4), 256>>>(3);
        seq_kernel<3><<<128, 128>>>(Wh);
        projR_kernel<<<dim3(64, 4, 2), 256>>>(Wo, out, 3);
        projC_kernel<<<dim3(64, 4, 3), 256>>>(3, 0);
        gsum_kernel<<<dim3(127, 4), 256>>>(2);
        seq_kernel<2><<<128, 128>>>(Wh);
        projR_kernel<<<dim3(128, 4, 2), 256>>>(Wo, out, 2);
        projC_kernel<<<dim3(128, 4, 2), 256>>>(2, 0);
        gsum_kernel<<<dim3(255, 4), 256>>>(1);
        seq_kernel<1><<<128, 128>>>(Wh);
        projR_kernel<<<dim3(256, 4, 2), 256>>>(Wo, out, 1);
        projC_kernel<<<dim3(256, 4, 1), 256>>>(1, 0);
        gsum_kernel<<<dim3(511, 4), 256>>>(0);
        seq_kernel<0><<<128, 128>>>(Wh);
        projR_kernel<<<dim3(512, 4, 2), 256>>>(Wo, out, 0);
        finalH_kernel<<<dim3(8, 4), 256>>>(out);
        return;
    }

    cudaStream_t s1 = s_s1, s2 = s_s2, s3 = s_s3;

    // Fork s1: packW (tiny, first) -> packX -> g0p bulk (levels 3..0).
    cudaEventRecord(s_ev0, 0);
    cudaStreamWaitEvent(s1, s_ev0, 0);
    packW_kernel<<<768, 256, 0, s1>>>(Wh, Wi, Wo);
    cudaEventRecord(s_evPk, s1);
    packX_kernel<<<8192, 256, 0, s1>>>(X);
    g0p_kernel<<<dim3(960, 4), 256, 0, s1>>>(Wi, Wh, 0);
    cudaEventRecord(s_evG0, s1);

    // Proj streams need packed weights.
    cudaStreamWaitEvent(s2, s_evPk, 0);
    cudaStreamWaitEvent(s3, s_evPk, 0);

    // Main: g0f (levels 7..4, float staging — no pack dependency).
    g0f_kernel<<<dim3(60, 4), 256>>>(X, Wi, Wh, 960);

    // ---- level 7 ----
    seq_kernel<7><<<128, 128>>>(Wh);
    cudaEventRecord(s_evH[7], 0);
    cudaStreamWaitEvent(s2, s_evH[7], 0);
    projR_kernel<<<dim3(4, 4, 2), 256, 0, s2>>>(Wo, out, 7);
    cudaStreamWaitEvent(s3, s_evH[7], 0);
    projC_kernel<<<dim3(4, 4, 6), 256, 0, s3>>>(7, 0);     // deferred z=0..5
    gsum_kernel<<<dim3(15, 4), 256, 0, s3>>>(5);
    cudaEventRecord(s_evGS[5], s3);
    cudaStreamWaitEvent(0, s_evPk, 0);                     // main projC needs WhP
    projC_kernel<<<dim3(4, 4, 1), 256>>>(7, 6);            // urgent z=6

    // ---- level 6 ----
    seq_kernel<6><<<128, 128>>>(Wh);
    cudaEventRecord(s_evH[6], 0);
    cudaStreamWaitEvent(s2, s_evH[6], 0);
    projR_kernel<<<dim3(8, 4, 2), 256, 0, s2>>>(Wo, out, 6);
    cudaStreamWaitEvent(s3, s_evH[6], 0);
    projC_kernel<<<dim3(8, 4, 5), 256, 0, s3>>>(6, 0);     // deferred z=0..4
    gsum_kernel<<<dim3(31, 4), 256, 0, s3>>>(4);
    cudaEventRecord(s_evGS[4], s3);
    projC_kernel<<<dim3(8, 4, 1), 256>>>(6, 5);            // urgent z=5

    // ---- level 5 ----
    cudaStreamWaitEvent(0, s_evGS[5], 0);
    seq_kernel<5><<<128, 128>>>(Wh);
    cudaEventRecord(s_evH[5], 0);
    cudaStreamWaitEvent(s2, s_evH[5], 0);
    projR_kernel<<<dim3(16, 4, 2), 256, 0, s2>>>(Wo, out, 5);
    cudaStreamWaitEvent(s3, s_evG0, 0);                    // gsum<3> reads g0p G
    cudaStreamWaitEvent(s3, s_evH[5], 0);
    projC_kernel<<<dim3(16, 4, 4), 256, 0, s3>>>(5, 0);    // deferred z=0..3
    gsum_kernel<<<dim3(63, 4), 256, 0, s3>>>(3);
    cudaEventRecord(s_evGS[3], s3);
    projC_kernel<<<dim3(16, 4, 1), 256>>>(5, 4);           // urgent z=4

    // ---- level 4 ----
    cudaStreamWaitEvent(0, s_evGS[4], 0);
    seq_kernel<4><<<128, 128>>>(Wh);
    cudaEventRecord(s_evH[4], 0);
    cudaStreamWaitEvent(s2, s_evH[4], 0);
    projR_kernel<<<dim3(32, 4, 2), 256, 0, s2>>>(Wo, out, 4);
    cudaStreamWaitEvent(s3, s_evH[4], 0);
    projC_kernel<<<dim3(32, 4, 3), 256, 0, s3>>>(4, 0);    // deferred z=0..2
    gsum_kernel<<<dim3(127, 4), 256, 0, s3>>>(2);
    cudaEventRecord(s_evGS[2], s3);
    projC_kernel<<<dim3(32, 4, 1), 256>>>(4, 3);           // urgent z=3

    // ---- level 3 ----
    cudaStreamWaitEvent(0, s_evGS[3], 0);
    seq_kernel<3><<<128, 128>>>(Wh);
    cudaEventRecord(s_evH[3], 0);
    cudaStreamWaitEvent(s2, s_evH[3], 0);
    projR_kernel<<<dim3(64, 4, 2), 256, 0, s2>>>(Wo, out, 3);
    cudaStreamWaitEvent(s3, s_evH[3], 0);
    projC_kernel<<<dim3(64, 4, 2), 256, 0, s3>>>(3, 0);    // deferred z=0..1
    gsum_kernel<<<dim3(255, 4), 256, 0, s3>>>(1);
    cudaEventRecord(s_evGS[1], s3);
    projC_kernel<<<dim3(64, 4, 1), 256>>>(3, 2);           // urgent z=2

    // ---- level 2 ----
    cudaStreamWaitEvent(0, s_evGS[2], 0);
    seq_kernel<2><<<128, 128>>>(Wh);
    cudaEventRecord(s_evH[2], 0);
    cudaStreamWaitEvent(s2, s_evH[2], 0);
    projR_kernel<<<dim3(128, 4, 2), 256, 0, s2>>>(Wo, out, 2);
    cudaStreamWaitEvent(s3, s_evH[2], 0);
    projC_kernel<<<dim3(128, 4, 1), 256, 0, s3>>>(2, 0);   // deferred z=0
    gsum_kernel<<<dim3(511, 4), 256, 0, s3>>>(0);
    cudaEventRecord(s_evGS[0], s3);
    projC_kernel<<<dim3(128, 4, 1), 256>>>(2, 1);          // urgent z=1

    // ---- level 1 ----
    cudaStreamWaitEvent(0, s_evGS[1], 0);
    seq_kernel<1><<<128, 128>>>(Wh);
    cudaEventRecord(s_evH[1], 0);
    cudaStreamWaitEvent(s2, s_evH[1], 0);
    projR_kernel<<<dim3(256, 4, 2), 256, 0, s2>>>(Wo, out, 1);
    projC_kernel<<<dim3(256, 4, 1), 256>>>(1, 0);          // urgent z=0

    // ---- level 0 ----
    cudaStreamWaitEvent(0, s_evGS[0], 0);
    seq_kernel<0><<<128, 128>>>(Wh);
    cudaEventRecord(s_evH[0], 0);
    cudaStreamWaitEvent(s2, s_evH[0], 0);
    projR_kernel<<<dim3(512, 4, 2), 256, 0, s2>>>(Wo, out, 0);  // writes Y
    cudaEventRecord(s_evR0, s2);

    finalH_kernel<<<dim3(8, 4), 256>>>(out);
    cudaStreamWaitEvent(0, s_evR0, 0);
}